// round 16
// baseline (speedup 1.0000x reference)
#include <cuda_runtime.h>
#include <cstdint>

// Problem constants (fixed instance)
constexpr int S   = 16;
constexpr int EXT = 64;
constexpr int SE  = S * EXT;          // 1024
constexpr int NN  = 8192;             // nodes
constexpr int EE  = 16384;            // edges
constexpr int PP  = 2048;             // paths
constexpr int MAXDEG = 64;            // safe cap (E[deg]=2, P(>64) ~ 0)

// Dense coefficients, duplicated float2 {c,c}, layout [kj][i] (i contiguous):
//   kj = k*16 + j
__device__ __align__(16) float2 g_C2i[256 * 16];
__device__ int g_cnt[NN];
__device__ int g_elist[NN * MAXDEG];

// ---------------- f32x2 packed helpers (sm_103a family) ----------------
__device__ __forceinline__ unsigned long long f32x2_pack(float lo, float hi) {
    unsigned long long d;
    asm("mov.b64 %0, {%1, %2};" : "=l"(d) : "f"(lo), "f"(hi));
    return d;
}
__device__ __forceinline__ void f32x2_unpack(unsigned long long v, float& lo, float& hi) {
    asm("mov.b64 {%0, %1}, %2;" : "=f"(lo), "=f"(hi) : "l"(v));
}
__device__ __forceinline__ unsigned long long f32x2_fma(unsigned long long a, unsigned long long b,
                                                        unsigned long long c) {
    unsigned long long d;
    asm("fma.rn.f32x2 %0, %1, %2, %3;" : "=l"(d) : "l"(a), "l"(b), "l"(c));
    return d;
}

// ---------------- setup kernels ----------------
__global__ void zero_meta_kernel() {
    int t = blockIdx.x * blockDim.x + threadIdx.x;
    if (t < 256 * 16) g_C2i[t] = make_float2(0.0f, 0.0f);
    if (t < NN) g_cnt[t] = 0;
}

__global__ void build_c_kernel(const int* __restrict__ path_indices,
                               const float* __restrict__ path_coeffs) {
    int p = blockIdx.x * blockDim.x + threadIdx.x;
    if (p >= PP) return;
    int i = path_indices[3 * p + 0];
    int j = path_indices[3 * p + 1];
    int k = path_indices[3 * p + 2];
    float cf = path_coeffs[p];
    int kj = k * S + j;
    atomicAdd(&g_C2i[kj * S + i].x, cf);
    atomicAdd(&g_C2i[kj * S + i].y, cf);
}

__global__ void fill_edges_kernel(const int* __restrict__ idx_in) {
    int e = blockIdx.x * blockDim.x + threadIdx.x;
    if (e >= EE) return;
    int n = idx_in[e];
    int pos = atomicAdd(&g_cnt[n], 1);
    if (pos < MAXDEG) g_elist[n * MAXDEG + pos] = e;
}

__global__ void zero_out_kernel(float4* __restrict__ out, int n4) {
    int t = blockIdx.x * blockDim.x + threadIdx.x;
    if (t < n4) out[t] = make_float4(0.0f, 0.0f, 0.0f, 0.0f);
}

// ---------------- main: fused two-stage per-node kernel ----------------
// Persistent blocks: 256 threads, 2 CTAs/SM. Per node n:
//   stage1: G[kj, c] = sum_i C[kj,i] * x[n,i,c]      (33.5M warp-FFMA2 chip)
//   stage2 per edge e with idx_in[e]==n:
//           out[idx_out[e], k, c] += sum_j G[k*16+j, c] * y[e,j,c]   (4.2M)
// Dynamic SMEM: C 32KB | G 64KB | x 4KB | y 4KB = 104KB.
constexpr int SMEM_BYTES = 32768 + 65536 + 4096 + 4096;

__global__ __launch_bounds__(256, 2) void seg_poly_2stage_kernel(
    const float* __restrict__ x,
    const float* __restrict__ y,
    const int*   __restrict__ idx_out,
    float*       __restrict__ out)
{
    extern __shared__ char smc[];
    float2* C2i = (float2*)smc;                       // [256 kj][16 i] dup
    float2* G2  = (float2*)(smc + 32768);             // [256 kj][32 cp]
    float2* x2s = (float2*)(smc + 32768 + 65536);     // [16 i][32 cp]
    float2* y2s = (float2*)(smc + 32768 + 65536 + 4096); // [16 j][32 cp]

    const int t = threadIdx.x;

    // load C once per block
    {
        const float4* src = (const float4*)g_C2i;
        float4* dst = (float4*)C2i;
        for (int q = t; q < (256 * 16) / 2; q += 256)
            dst[q] = src[q];
    }
    const int cp2 = t & 15;        // stage1: c-pair half (owns cp2 and cp2+16)
    const int kq  = t >> 4;        // stage1: kj-group (16 kj each)
    const int cp  = t & 31;        // stage2: c-pair (c, c+32)
    const int k2  = t >> 5;        // stage2: k-pair (2*k2, 2*k2+1)
    __syncthreads();

    for (int n = blockIdx.x; n < NN; n += gridDim.x) {
        const int deg0 = g_cnt[n];
        const int deg  = deg0 < MAXDEG ? deg0 : MAXDEG;
        if (deg == 0) continue;                   // uniform per block

        // ---- stage x into SMEM (coalesced) ----
        const float* xr = x + (size_t)n * SE;
        for (int q = t; q < 512; q += 256) {
            int i = q >> 5, cc = q & 31;
            x2s[q] = make_float2(xr[i * 64 + cc], xr[i * 64 + cc + 32]);
        }
        __syncthreads();   // also: all threads done with previous node

        // ---- stage 1: G = C * x ----
        unsigned long long xA[16], xB[16];
        #pragma unroll
        for (int i = 0; i < 16; ++i) {
            xA[i] = *(const unsigned long long*)&x2s[i * 32 + cp2];
            xB[i] = *(const unsigned long long*)&x2s[i * 32 + cp2 + 16];
        }
        const int kjb = kq * 16;
        #pragma unroll 4
        for (int kk = 0; kk < 16; ++kk) {
            const int kj = kjb + kk;
            const ulonglong2* c128 = (const ulonglong2*)(C2i + kj * 16);
            unsigned long long aA = 0ULL, aB = 0ULL;
            #pragma unroll
            for (int i2 = 0; i2 < 8; ++i2) {
                ulonglong2 cc = c128[i2];          // LDS.128 broadcast
                aA = f32x2_fma(cc.x, xA[2 * i2],     aA);
                aA = f32x2_fma(cc.y, xA[2 * i2 + 1], aA);
                aB = f32x2_fma(cc.x, xB[2 * i2],     aB);
                aB = f32x2_fma(cc.y, xB[2 * i2 + 1], aB);
            }
            *(unsigned long long*)&G2[kj * 32 + cp2]      = aA;
            *(unsigned long long*)&G2[kj * 32 + cp2 + 16] = aB;
        }

        // ---- stage 2: per edge ----
        for (int eo = 0; eo < deg; ++eo) {
            const int e = g_elist[n * MAXDEG + eo];
            __syncthreads();   // G2 ready (eo=0) / y2s consumers done (eo>0)
            const float* yr = y + (size_t)e * SE;
            for (int q = t; q < 512; q += 256) {
                int j = q >> 5, cc = q & 31;
                y2s[q] = make_float2(yr[j * 64 + cc], yr[j * 64 + cc + 32]);
            }
            __syncthreads();

            const unsigned long long* gp0 =
                (const unsigned long long*)(G2 + (k2 * 2) * 16 * 32 + cp);
            const unsigned long long* gp1 = gp0 + 16 * 32;
            unsigned long long a0 = 0ULL, a1 = 0ULL;
            #pragma unroll
            for (int j = 0; j < 16; ++j) {
                const unsigned long long yv =
                    *(const unsigned long long*)&y2s[j * 32 + cp];
                a0 = f32x2_fma(gp0[j * 32], yv, a0);
                a1 = f32x2_fma(gp1[j * 32], yv, a1);
            }
            const int orow = idx_out[e];
            float* op = out + (size_t)orow * SE;
            float l0, h0, l1, h1;
            f32x2_unpack(a0, l0, h0);
            f32x2_unpack(a1, l1, h1);
            const int k0 = k2 * 2, k1 = k0 + 1;
            atomicAdd(op + k0 * 64 + cp,      l0);
            atomicAdd(op + k0 * 64 + cp + 32, h0);
            atomicAdd(op + k1 * 64 + cp,      l1);
            atomicAdd(op + k1 * 64 + cp + 32, h1);
        }
    }
}

// ---------------- launch ----------------
extern "C" void kernel_launch(void* const* d_in, const int* in_sizes, int n_in,
                              void* d_out, int out_size)
{
    const float* x        = (const float*)d_in[0];
    const float* y        = (const float*)d_in[1];
    const int*   idx_in   = (const int*)d_in[2];
    const int*   idx_out  = (const int*)d_in[3];
    const int*   path_idx = (const int*)d_in[4];
    const float* path_cf  = (const float*)d_in[5];
    float* out = (float*)d_out;

    static bool attr_set = false;
    if (!attr_set) {
        cudaFuncSetAttribute(seg_poly_2stage_kernel,
                             cudaFuncAttributeMaxDynamicSharedMemorySize,
                             SMEM_BYTES);
        attr_set = true;
    }

    zero_meta_kernel<<<(NN + 255) / 256, 256>>>();
    build_c_kernel<<<(PP + 255) / 256, 256>>>(path_idx, path_cf);
    fill_edges_kernel<<<(EE + 255) / 256, 256>>>(idx_in);

    int n4 = out_size / 4;
    zero_out_kernel<<<(n4 + 511) / 512, 512>>>((float4*)d_out, n4);

    seg_poly_2stage_kernel<<<304, 256, SMEM_BYTES>>>(x, y, idx_out, out);
}

// round 17
// speedup vs baseline: 1.2130x; 1.2130x over previous
#include <cuda_runtime.h>
#include <cstdint>

// Problem constants (fixed instance)
constexpr int S   = 16;
constexpr int EXT = 64;
constexpr int SE  = S * EXT;          // 1024
constexpr int NN  = 8192;             // nodes
constexpr int EE  = 16384;            // edges
constexpr int PP  = 2048;             // paths
constexpr int MAXDEG = 64;            // safe cap (E[deg]=2)

// Dense coefficients, duplicated float2 {c,c}, layout [kj][i] (i contiguous)
__device__ __align__(16) float2 g_C2i[256 * 16];
__device__ int g_cnt[NN];
__device__ int g_elist[NN * MAXDEG];

// ---------------- f32x2 packed helpers ----------------
__device__ __forceinline__ unsigned long long f32x2_pack(float lo, float hi) {
    unsigned long long d;
    asm("mov.b64 %0, {%1, %2};" : "=l"(d) : "f"(lo), "f"(hi));
    return d;
}
__device__ __forceinline__ void f32x2_unpack(unsigned long long v, float& lo, float& hi) {
    asm("mov.b64 {%0, %1}, %2;" : "=f"(lo), "=f"(hi) : "l"(v));
}
__device__ __forceinline__ unsigned long long f32x2_fma(unsigned long long a, unsigned long long b,
                                                        unsigned long long c) {
    unsigned long long d;
    asm("fma.rn.f32x2 %0, %1, %2, %3;" : "=l"(d) : "l"(a), "l"(b), "l"(c));
    return d;
}

// ---------------- setup kernels ----------------
__global__ void zero_meta_kernel() {
    int t = blockIdx.x * blockDim.x + threadIdx.x;
    if (t < 256 * 16) g_C2i[t] = make_float2(0.0f, 0.0f);
    if (t < NN) g_cnt[t] = 0;
}

__global__ void build_c_kernel(const int* __restrict__ path_indices,
                               const float* __restrict__ path_coeffs) {
    int p = blockIdx.x * blockDim.x + threadIdx.x;
    if (p >= PP) return;
    int i = path_indices[3 * p + 0];
    int j = path_indices[3 * p + 1];
    int k = path_indices[3 * p + 2];
    float cf = path_coeffs[p];
    int kj = k * S + j;
    atomicAdd(&g_C2i[kj * S + i].x, cf);
    atomicAdd(&g_C2i[kj * S + i].y, cf);
}

__global__ void fill_edges_kernel(const int* __restrict__ idx_in) {
    int e = blockIdx.x * blockDim.x + threadIdx.x;
    if (e >= EE) return;
    int n = idx_in[e];
    int pos = atomicAdd(&g_cnt[n], 1);
    if (pos < MAXDEG) g_elist[n * MAXDEG + pos] = e;
}

__global__ void zero_out_kernel(float4* __restrict__ out, int n4) {
    int t = blockIdx.x * blockDim.x + threadIdx.x;
    if (t < n4) out[t] = make_float4(0.0f, 0.0f, 0.0f, 0.0f);
}

// ---------------- main: fused two-stage, 2 barriers/node ----------------
// Persistent blocks (304 x 256 thr, 2 CTAs/SM). Per node n:
//   stage x + edge-list into SMEM        (1 barrier: data ready AND previous
//                                         stage2 done reading G2)
//   stage1: G[kj,c] = sum_i C[kj,i]*x[n,i,c]   (1 barrier: G published)
//   stage2: per edge, y read DIRECT from gmem (no staging, no barriers),
//           out[idx_out[e],k,c] += sum_j G[k*16+j,c]*y[e,j,c]
// SMEM: C 32KB | G 64KB | x 4KB | els 256B
constexpr int SMEM_BYTES = 32768 + 65536 + 4096 + 256;

__global__ __launch_bounds__(256, 2) void seg_poly_2stage_kernel(
    const float* __restrict__ x,
    const float* __restrict__ y,
    const int*   __restrict__ idx_out,
    float*       __restrict__ out)
{
    extern __shared__ char smc[];
    float2* C2i = (float2*)smc;                          // [256 kj][16 i] dup
    float2* G2  = (float2*)(smc + 32768);                // [256 kj][32 cp]
    float2* x2s = (float2*)(smc + 32768 + 65536);        // [16 i][32 cp]
    int*    els = (int*)   (smc + 32768 + 65536 + 4096); // [MAXDEG]

    const int t = threadIdx.x;

    // load C once per block
    {
        const float4* src = (const float4*)g_C2i;
        float4* dst = (float4*)C2i;
        for (int q = t; q < (256 * 16) / 2; q += 256)
            dst[q] = src[q];
    }
    const int cp2 = t & 15;        // stage1: c-pair half (owns cp2, cp2+16)
    const int kq  = t >> 4;        // stage1: kj-group of 16
    const int cp  = t & 31;        // stage2: c-pair (c, c+32)
    const int k2  = t >> 5;        // stage2: k-pair (2*k2, 2*k2+1)
    __syncthreads();

    for (int n = blockIdx.x; n < NN; n += gridDim.x) {
        const int deg0 = g_cnt[n];
        const int deg  = deg0 < MAXDEG ? deg0 : MAXDEG;
        if (deg == 0) continue;                   // uniform per block

        // ---- stage x + edge list into SMEM ----
        // (x2s/els last read before the G-publish barrier of the previous
        //  node -> safe to overwrite without an extra barrier)
        const float* xr = x + (size_t)n * SE;
        for (int q = t; q < 512; q += 256) {
            int i = q >> 5, cc = q & 31;
            x2s[q] = make_float2(xr[i * 64 + cc], xr[i * 64 + cc + 32]);
        }
        for (int q = t; q < deg; q += 256)
            els[q] = g_elist[n * MAXDEG + q];
        __syncthreads();   // x/els ready; previous stage2 done with G2

        // ---- stage 1: G = C * x ----
        unsigned long long xA[16], xB[16];
        #pragma unroll
        for (int i = 0; i < 16; ++i) {
            xA[i] = *(const unsigned long long*)&x2s[i * 32 + cp2];
            xB[i] = *(const unsigned long long*)&x2s[i * 32 + cp2 + 16];
        }
        const int kjb = kq * 16;
        #pragma unroll 4
        for (int kk = 0; kk < 16; ++kk) {
            const int kj = kjb + kk;
            const ulonglong2* c128 = (const ulonglong2*)(C2i + kj * 16);
            unsigned long long aA = 0ULL, aB = 0ULL;
            #pragma unroll
            for (int i2 = 0; i2 < 8; ++i2) {
                ulonglong2 cc = c128[i2];          // LDS.128 broadcast
                aA = f32x2_fma(cc.x, xA[2 * i2],     aA);
                aA = f32x2_fma(cc.y, xA[2 * i2 + 1], aA);
                aB = f32x2_fma(cc.x, xB[2 * i2],     aB);
                aB = f32x2_fma(cc.y, xB[2 * i2 + 1], aB);
            }
            *(unsigned long long*)&G2[kj * 32 + cp2]      = aA;
            *(unsigned long long*)&G2[kj * 32 + cp2 + 16] = aB;
        }
        __syncthreads();   // G2 published

        // ---- stage 2: per edge, no barriers ----
        const unsigned long long* gp0 =
            (const unsigned long long*)&G2[(k2 * 2) * 16 * 32 + cp];
        const unsigned long long* gp1 = gp0 + 16 * 32;

        for (int eo = 0; eo < deg; ++eo) {
            const int e = els[eo];                 // LDS hit
            const int orow = idx_out[e];
            const float* yr = y + (size_t)e * SE + cp;

            // batch the 32 y loads first (high MLP), then contract
            unsigned long long yv[16];
            #pragma unroll
            for (int j = 0; j < 16; ++j)
                yv[j] = f32x2_pack(yr[j * 64], yr[j * 64 + 32]);

            unsigned long long a0 = 0ULL, a1 = 0ULL;
            #pragma unroll
            for (int j = 0; j < 16; ++j) {
                a0 = f32x2_fma(gp0[j * 32], yv[j], a0);
                a1 = f32x2_fma(gp1[j * 32], yv[j], a1);
            }

            float* op = out + (size_t)orow * SE;
            float l0, h0, l1, h1;
            f32x2_unpack(a0, l0, h0);
            f32x2_unpack(a1, l1, h1);
            const int k0 = k2 * 2, k1 = k0 + 1;
            atomicAdd(op + k0 * 64 + cp,      l0);
            atomicAdd(op + k0 * 64 + cp + 32, h0);
            atomicAdd(op + k1 * 64 + cp,      l1);
            atomicAdd(op + k1 * 64 + cp + 32, h1);
        }
    }
}

// ---------------- launch ----------------
extern "C" void kernel_launch(void* const* d_in, const int* in_sizes, int n_in,
                              void* d_out, int out_size)
{
    const float* x        = (const float*)d_in[0];
    const float* y        = (const float*)d_in[1];
    const int*   idx_in   = (const int*)d_in[2];
    const int*   idx_out  = (const int*)d_in[3];
    const int*   path_idx = (const int*)d_in[4];
    const float* path_cf  = (const float*)d_in[5];
    float* out = (float*)d_out;

    static bool attr_set = false;
    if (!attr_set) {
        cudaFuncSetAttribute(seg_poly_2stage_kernel,
                             cudaFuncAttributeMaxDynamicSharedMemorySize,
                             SMEM_BYTES);
        attr_set = true;
    }

    zero_meta_kernel<<<(NN + 255) / 256, 256>>>();
    build_c_kernel<<<(PP + 255) / 256, 256>>>(path_idx, path_cf);
    fill_edges_kernel<<<(EE + 255) / 256, 256>>>(idx_in);

    int n4 = out_size / 4;
    zero_out_kernel<<<(n4 + 511) / 512, 512>>>((float4*)d_out, n4);

    seg_poly_2stage_kernel<<<304, 256, SMEM_BYTES>>>(x, y, idx_out, out);
}